// round 5
// baseline (speedup 1.0000x reference)
#include <cuda_runtime.h>
#include <cuda_bf16.h>
#include <math.h>
#include <stdint.h>

// Problem dims
#define BB 32
#define TT 12
#define NN 325
#define DD 128
#define HH 8
#define HDM 16
#define FF 512
#define TOK (BB*TT*NN)   // 124800

// ---------------- scratch (static device memory; no allocs) ----------------
__device__ float          g_qkv [(size_t)TOK * 384];
__device__ float          g_proj[(size_t)TOK * DD];
__device__ float          g_x1  [(size_t)TOK * DD];
__device__ float          g_x2  [(size_t)TOK * DD];
__device__ __nv_bfloat16  g_xh  [(size_t)TOK * DD];
__device__ __nv_bfloat16  g_xl  [(size_t)TOK * DD];
__device__ __nv_bfloat16  g_atth[(size_t)TOK * DD];
__device__ __nv_bfloat16  g_attl[(size_t)TOK * DD];
__device__ __nv_bfloat16  g_hh  [(size_t)TOK * FF];
__device__ __nv_bfloat16  g_hl  [(size_t)TOK * FF];
__device__ __nv_bfloat16  g_wh  [262144];
__device__ __nv_bfloat16  g_wl  [262144];

// weight split offsets within g_wh/g_wl
#define WO_TWIN  0
#define WO_TWOUT 49152
#define WO_SWIN  65536
#define WO_SWOUT 114688
#define WO_FFW1  131072
#define WO_FFW2  196608

// ---------------- helpers ----------------
__device__ __forceinline__ uint32_t smem_to_u32(const void* p) {
    uint32_t a;
    asm("{ .reg .u64 t; cvta.to.shared.u64 t, %1; cvt.u32.u64 %0, t; }" : "=r"(a) : "l"(p));
    return a;
}
#define SMEM_SWIZZLE_128B(o) ((o) ^ (((o) >> 3) & 0x70))

__device__ __forceinline__ void ldsm_x4(uint32_t& r0, uint32_t& r1, uint32_t& r2, uint32_t& r3,
                                        uint32_t addr) {
    asm volatile("ldmatrix.sync.aligned.m8n8.x4.shared.b16 {%0,%1,%2,%3}, [%4];"
                 : "=r"(r0), "=r"(r1), "=r"(r2), "=r"(r3) : "r"(addr));
}
__device__ __forceinline__ void mma_bf16(float* c, const uint32_t* a, const uint32_t* b) {
    asm volatile("mma.sync.aligned.m16n8k16.row.col.f32.bf16.bf16.f32 "
                 "{%0,%1,%2,%3}, {%4,%5,%6,%7}, {%8,%9}, {%0,%1,%2,%3};"
                 : "+f"(c[0]), "+f"(c[1]), "+f"(c[2]), "+f"(c[3])
                 : "r"(a[0]), "r"(a[1]), "r"(a[2]), "r"(a[3]), "r"(b[0]), "r"(b[1]));
}

__device__ __forceinline__ float gelu_tanh(float x) {
    const float k0 = 0.7978845608028654f;
    float x3 = x * x * x;
    return 0.5f * x * (1.0f + tanhf(k0 * (x + 0.044715f * x3)));
}
__device__ __forceinline__ void split_bf16(float v, __nv_bfloat16& hi, __nv_bfloat16& lo) {
    hi = __float2bfloat16(v);
    lo = __float2bfloat16(v - __bfloat162float(hi));
}

// ---------------- fp32 -> bf16 hi/lo split ----------------
__global__ void conv_split(const float* __restrict__ in,
                           __nv_bfloat16* __restrict__ hi, __nv_bfloat16* __restrict__ lo, int n)
{
    int i = blockIdx.x * 256 + threadIdx.x;
    if (i < n) {
        __nv_bfloat16 h, l;
        split_bf16(in[i], h, l);
        hi[i] = h; lo[i] = l;
    }
}

// ---------------- HMMA GEMM: C[M,N] = (Ah+Al)[M,K] @ (Wh+Wl)[N,K]^T + bias ----------------
// Block tile 128x64, 8 warps (4m x 2n), warp tile 32x32, K-chunk 64.
// 3-term Markidis split accumulated in fp32 registers.
#define SA_H 0
#define SA_L 16384
#define SW_H 32768
#define SW_L 40960
#define GEMM_SMEM 49152   // tiles exactly 48KB; f32 stage (128*65*4=33280B) reuses it

__global__ __launch_bounds__(256) void gemm_mma(
    const __nv_bfloat16* __restrict__ Ah, const __nv_bfloat16* __restrict__ Al,
    const __nv_bfloat16* __restrict__ Wh, const __nv_bfloat16* __restrict__ Wl,
    const float* __restrict__ bias,
    float* __restrict__ Cf, __nv_bfloat16* __restrict__ Ch, __nv_bfloat16* __restrict__ Cl,
    int M, int N, int K, int act)
{
    extern __shared__ char smem[];
    const uint32_t sbase = smem_to_u32(smem);
    const int tid  = threadIdx.x;
    const int wid  = tid >> 5;
    const int lane = tid & 31;
    const int wm   = wid >> 1;        // 0..3  (32-row slab)
    const int wn   = wid & 1;         // 0..1  (32-col slab)
    const int bm   = blockIdx.x * 128;
    const int bn   = blockIdx.y * 64;

    float acc[2][4][4];               // [mtile][ntile][4]
    #pragma unroll
    for (int i = 0; i < 2; i++)
        #pragma unroll
        for (int j = 0; j < 4; j++)
            #pragma unroll
            for (int k = 0; k < 4; k++) acc[i][j][k] = 0.0f;

    const int nchunks = K >> 6;
    for (int c = 0; c < nchunks; c++) {
        const int kbase = c << 6;
        // ---- stage tiles into SMEM (SW128 swizzle, 128B rows of 64 bf16) ----
        #pragma unroll
        for (int j = 0; j < 4; j++) {                 // A tiles: 128 rows x 8 groups
            int u = tid + j * 256;
            int r = u >> 3, g = u & 7;
            uint32_t sw = SMEM_SWIZZLE_128B((uint32_t)(r * 128 + g * 16));
            size_t ga = (size_t)(bm + r) * K + kbase + g * 8;
            *(uint4*)(smem + SA_H + sw) = *(const uint4*)(Ah + ga);
            *(uint4*)(smem + SA_L + sw) = *(const uint4*)(Al + ga);
        }
        #pragma unroll
        for (int j = 0; j < 2; j++) {                 // W tiles: 64 rows x 8 groups
            int u = tid + j * 256;
            int r = u >> 3, g = u & 7;
            uint32_t sw = SMEM_SWIZZLE_128B((uint32_t)(r * 128 + g * 16));
            size_t gw = (size_t)(bn + r) * K + kbase + g * 8;
            *(uint4*)(smem + SW_H + sw) = *(const uint4*)(Wh + gw);
            *(uint4*)(smem + SW_L + sw) = *(const uint4*)(Wl + gw);
        }
        __syncthreads();

        // ---- compute: 4 k-slabs of 16 ----
        #pragma unroll
        for (int ks = 0; ks < 4; ks++) {
            const int k0 = ks * 16;
            // A fragments (hi & lo): 2 m-tiles
            uint32_t ah[2][4], al[2][4];
            #pragma unroll
            for (int mt = 0; mt < 2; mt++) {
                int row = wm * 32 + mt * 16 + (lane & 15);
                int kc  = k0 + ((lane >> 4) << 3);
                uint32_t off = SMEM_SWIZZLE_128B((uint32_t)(row * 128 + kc * 2));
                ldsm_x4(ah[mt][0], ah[mt][1], ah[mt][2], ah[mt][3], sbase + SA_H + off);
                ldsm_x4(al[mt][0], al[mt][1], al[mt][2], al[mt][3], sbase + SA_L + off);
            }
            // B fragments (hi & lo): 4 n-tiles, 2 per ldmatrix.x4
            uint32_t bh[4][2], bl[4][2];
            #pragma unroll
            for (int pair = 0; pair < 2; pair++) {
                int n  = wn * 32 + pair * 16 + ((lane >> 4) << 3) + (lane & 7);
                int kc = k0 + ((lane >> 3) & 1) * 8;
                uint32_t off = SMEM_SWIZZLE_128B((uint32_t)(n * 128 + kc * 2));
                uint32_t r0, r1, r2, r3;
                ldsm_x4(r0, r1, r2, r3, sbase + SW_H + off);
                bh[pair * 2][0] = r0; bh[pair * 2][1] = r1;
                bh[pair * 2 + 1][0] = r2; bh[pair * 2 + 1][1] = r3;
                ldsm_x4(r0, r1, r2, r3, sbase + SW_L + off);
                bl[pair * 2][0] = r0; bl[pair * 2][1] = r1;
                bl[pair * 2 + 1][0] = r2; bl[pair * 2 + 1][1] = r3;
            }
            // 3-term product
            #pragma unroll
            for (int mt = 0; mt < 2; mt++)
                #pragma unroll
                for (int nt = 0; nt < 4; nt++) {
                    mma_bf16(acc[mt][nt], ah[mt], bh[nt]);
                    mma_bf16(acc[mt][nt], al[mt], bh[nt]);
                    mma_bf16(acc[mt][nt], ah[mt], bl[nt]);
                }
        }
        __syncthreads();
    }

    // ---- epilogue: regs -> stride-65 f32 stage -> coalesced gmem ----
    float* sst = (float*)smem;
    #pragma unroll
    for (int mt = 0; mt < 2; mt++) {
        int row0 = wm * 32 + mt * 16 + (lane >> 2);
        #pragma unroll
        for (int nt = 0; nt < 4; nt++) {
            int col0 = wn * 32 + nt * 8 + (lane & 3) * 2;
            sst[row0 * 65 + col0]           = acc[mt][nt][0];
            sst[row0 * 65 + col0 + 1]       = acc[mt][nt][1];
            sst[(row0 + 8) * 65 + col0]     = acc[mt][nt][2];
            sst[(row0 + 8) * 65 + col0 + 1] = acc[mt][nt][3];
        }
    }
    __syncthreads();

    #pragma unroll
    for (int j = 0; j < 8; j++) {
        int i   = tid + j * 256;          // 0..2047, 4 cols each
        int row = i >> 4;
        int col = (i & 15) * 4;
        float v0 = sst[row * 65 + col]     + bias[bn + col];
        float v1 = sst[row * 65 + col + 1] + bias[bn + col + 1];
        float v2 = sst[row * 65 + col + 2] + bias[bn + col + 2];
        float v3 = sst[row * 65 + col + 3] + bias[bn + col + 3];
        if (act) { v0 = gelu_tanh(v0); v1 = gelu_tanh(v1); v2 = gelu_tanh(v2); v3 = gelu_tanh(v3); }
        size_t gi = (size_t)(bm + row) * N + bn + col;
        if (Cf) *(float4*)(Cf + gi) = make_float4(v0, v1, v2, v3);
        if (Ch) {
            __nv_bfloat16 h0, l0, h1, l1, h2, l2, h3, l3;
            split_bf16(v0, h0, l0); split_bf16(v1, h1, l1);
            split_bf16(v2, h2, l2); split_bf16(v3, h3, l3);
            __nv_bfloat162 hh01; hh01.x = h0; hh01.y = h1;
            __nv_bfloat162 hh23; hh23.x = h2; hh23.y = h3;
            __nv_bfloat162 ll01; ll01.x = l0; ll01.y = l1;
            __nv_bfloat162 ll23; ll23.x = l2; ll23.y = l3;
            *(__nv_bfloat162*)(Ch + gi)     = hh01;
            *(__nv_bfloat162*)(Ch + gi + 2) = hh23;
            *(__nv_bfloat162*)(Cl + gi)     = ll01;
            *(__nv_bfloat162*)(Cl + gi + 2) = ll23;
        }
    }
}

// ---------------- temporal attention: block per (b, n), all 8 heads, T=12 ----------------
__global__ void temporal_attn(const float* __restrict__ qkv,
                              __nv_bfloat16* __restrict__ atth, __nv_bfloat16* __restrict__ attl)
{
    const int b = blockIdx.x / NN;
    const int n = blockIdx.x % NN;
    const int tid = threadIdx.x;

    __shared__ float s_qkv[TT][384];
    __shared__ float s_p[HH][TT][TT];

    for (int e = tid; e < TT * 384; e += 256) {
        int t = e / 384, c = e % 384;
        s_qkv[t][c] = qkv[((size_t)((b * TT + t) * NN + n)) * 384 + c];
    }
    __syncthreads();

    for (int e = tid; e < HH * TT * TT; e += 256) {
        int h = e / (TT * TT);
        int r = (e / TT) % TT;
        int c = e % TT;
        float s = 0.0f;
        #pragma unroll
        for (int d = 0; d < HDM; d++)
            s = fmaf(s_qkv[r][h * HDM + d], s_qkv[c][128 + h * HDM + d], s);
        s_p[h][r][c] = s * 0.25f;
    }
    __syncthreads();

    if (tid < HH * TT) {
        int h = tid / TT, r = tid % TT;
        float m = -INFINITY;
        #pragma unroll
        for (int c = 0; c < TT; c++) m = fmaxf(m, s_p[h][r][c]);
        float sum = 0.0f;
        #pragma unroll
        for (int c = 0; c < TT; c++) {
            float p = expf(s_p[h][r][c] - m);
            s_p[h][r][c] = p;
            sum += p;
        }
        float inv = 1.0f / sum;
        #pragma unroll
        for (int c = 0; c < TT; c++) s_p[h][r][c] *= inv;
    }
    __syncthreads();

    for (int e = tid; e < HH * TT * HDM; e += 256) {
        int h = e / (TT * HDM);
        int r = (e / HDM) % TT;
        int d = e % HDM;
        float o = 0.0f;
        #pragma unroll
        for (int c = 0; c < TT; c++)
            o = fmaf(s_p[h][r][c], s_qkv[c][256 + h * HDM + d], o);
        size_t gi = ((size_t)((b * TT + r) * NN + n)) * DD + h * HDM + d;
        __nv_bfloat16 hh, ll;
        split_bf16(o, hh, ll);
        atth[gi] = hh; attl[gi] = ll;
    }
}

// ---------------- spatial attention: block per (bt, h), N=325, graph bias ----------------
__global__ void spatial_attn(const float* __restrict__ qkv,
                             const float* __restrict__ bias,
                             __nv_bfloat16* __restrict__ atth, __nv_bfloat16* __restrict__ attl)
{
    const int bt = blockIdx.x / HH;
    const int h  = blockIdx.x % HH;
    const int tid = threadIdx.x;
    const int warp = tid >> 5;
    const int lane = tid & 31;

    __shared__ float s_k[NN][17];
    __shared__ float s_v[NN][17];

    for (int e = tid; e < NN * HDM; e += 256) {
        int n = e / HDM, d = e % HDM;
        const float* row = qkv + ((size_t)(bt * NN + n)) * 384;
        s_k[n][d] = row[128 + h * HDM + d];
        s_v[n][d] = row[256 + h * HDM + d];
    }
    __syncthreads();

    for (int qi = warp; qi < NN; qi += 8) {
        const float* qrow = qkv + ((size_t)(bt * NN + qi)) * 384 + h * HDM;
        float q[HDM];
        #pragma unroll
        for (int d = 0; d < HDM; d++) q[d] = qrow[d];

        float s[11];
        float m = -INFINITY;
        #pragma unroll
        for (int i = 0; i < 11; i++) {
            int j = lane + 32 * i;
            if (j < NN) {
                float a = 0.0f;
                #pragma unroll
                for (int d = 0; d < HDM; d++) a = fmaf(q[d], s_k[j][d], a);
                s[i] = a * 0.25f + bias[qi * NN + j];
            } else {
                s[i] = -INFINITY;
            }
            m = fmaxf(m, s[i]);
        }
        #pragma unroll
        for (int o = 16; o; o >>= 1) m = fmaxf(m, __shfl_xor_sync(0xffffffffu, m, o));

        float p[11];
        float sum = 0.0f;
        #pragma unroll
        for (int i = 0; i < 11; i++) { p[i] = expf(s[i] - m); sum += p[i]; }
        #pragma unroll
        for (int o = 16; o; o >>= 1) sum += __shfl_xor_sync(0xffffffffu, sum, o);
        float inv = 1.0f / sum;

        float acc[HDM];
        #pragma unroll
        for (int d = 0; d < HDM; d++) acc[d] = 0.0f;
        #pragma unroll
        for (int i = 0; i < 11; i++) {
            int j = lane + 32 * i;
            if (j < NN) {
                #pragma unroll
                for (int d = 0; d < HDM; d++) acc[d] = fmaf(p[i], s_v[j][d], acc[d]);
            }
        }
        #pragma unroll
        for (int d = 0; d < HDM; d++)
            #pragma unroll
            for (int o = 16; o; o >>= 1)
                acc[d] += __shfl_xor_sync(0xffffffffu, acc[d], o);

        if (lane < HDM) {
            float myv = 0.0f;
            #pragma unroll
            for (int d = 0; d < HDM; d++) if (lane == d) myv = acc[d];
            float v = myv * inv;
            size_t gi = ((size_t)(bt * NN + qi)) * DD + h * HDM + lane;
            __nv_bfloat16 hh, ll;
            split_bf16(v, hh, ll);
            atth[gi] = hh; attl[gi] = ll;
        }
    }
}

// ---------------- residual + layernorm (+ optional bf16 hi/lo emit) ----------------
__global__ void add_ln(const float* __restrict__ x, const float* __restrict__ r,
                       const float* __restrict__ g, const float* __restrict__ b,
                       float* __restrict__ out,
                       __nv_bfloat16* __restrict__ oh, __nv_bfloat16* __restrict__ ol)
{
    const int warp = threadIdx.x >> 5;
    const int lane = threadIdx.x & 31;
    const size_t tok = (size_t)blockIdx.x * 8 + warp;

    const float4 xv = ((const float4*)x)[tok * 32 + lane];
    const float4 rv = ((const float4*)r)[tok * 32 + lane];
    float v0 = xv.x + rv.x, v1 = xv.y + rv.y, v2 = xv.z + rv.z, v3 = xv.w + rv.w;

    float sum = v0 + v1 + v2 + v3;
    float sq  = v0*v0 + v1*v1 + v2*v2 + v3*v3;
    #pragma unroll
    for (int o = 16; o; o >>= 1) {
        sum += __shfl_xor_sync(0xffffffffu, sum, o);
        sq  += __shfl_xor_sync(0xffffffffu, sq, o);
    }
    float mean = sum * (1.0f / 128.0f);
    float var  = sq * (1.0f / 128.0f) - mean * mean;
    float rstd = rsqrtf(var + 1e-5f);

    const float4 gv = ((const float4*)g)[lane];
    const float4 bv = ((const float4*)b)[lane];
    float4 ov;
    ov.x = (v0 - mean) * rstd * gv.x + bv.x;
    ov.y = (v1 - mean) * rstd * gv.y + bv.y;
    ov.z = (v2 - mean) * rstd * gv.z + bv.z;
    ov.w = (v3 - mean) * rstd * gv.w + bv.w;
    ((float4*)out)[tok * 32 + lane] = ov;

    if (oh) {
        size_t base = tok * 128 + (size_t)lane * 4;
        __nv_bfloat16 h, l;
        split_bf16(ov.x, h, l); oh[base + 0] = h; ol[base + 0] = l;
        split_bf16(ov.y, h, l); oh[base + 1] = h; ol[base + 1] = l;
        split_bf16(ov.z, h, l); oh[base + 2] = h; ol[base + 2] = l;
        split_bf16(ov.w, h, l); oh[base + 3] = h; ol[base + 3] = l;
    }
}

// ---------------- launcher ----------------
extern "C" void kernel_launch(void* const* d_in, const int* in_sizes, int n_in,
                              void* d_out, int out_size)
{
    const float* x        = (const float*)d_in[0];
    const float* t_w_in   = (const float*)d_in[1];
    const float* t_b_in   = (const float*)d_in[2];
    const float* t_w_out  = (const float*)d_in[3];
    const float* t_b_out  = (const float*)d_in[4];
    const float* s_w_in   = (const float*)d_in[5];
    const float* s_b_in   = (const float*)d_in[6];
    const float* s_w_out  = (const float*)d_in[7];
    const float* s_b_out  = (const float*)d_in[8];
    const float* gbias    = (const float*)d_in[9];
    const float* norm_t_g = (const float*)d_in[10];
    const float* norm_t_b = (const float*)d_in[11];
    const float* norm_s_g = (const float*)d_in[12];
    const float* norm_s_b = (const float*)d_in[13];
    const float* ff_w1    = (const float*)d_in[14];
    const float* ff_b1    = (const float*)d_in[15];
    const float* ff_w2    = (const float*)d_in[16];
    const float* ff_b2    = (const float*)d_in[17];
    const float* norm_f_g = (const float*)d_in[18];
    const float* norm_f_b = (const float*)d_in[19];
    float* out = (float*)d_out;

    float *qkv, *proj, *x1, *x2;
    __nv_bfloat16 *xh, *xl, *atth, *attl, *hh, *hl, *wh, *wl;
    cudaGetSymbolAddress((void**)&qkv,  g_qkv);
    cudaGetSymbolAddress((void**)&proj, g_proj);
    cudaGetSymbolAddress((void**)&x1,   g_x1);
    cudaGetSymbolAddress((void**)&x2,   g_x2);
    cudaGetSymbolAddress((void**)&xh,   g_xh);
    cudaGetSymbolAddress((void**)&xl,   g_xl);
    cudaGetSymbolAddress((void**)&atth, g_atth);
    cudaGetSymbolAddress((void**)&attl, g_attl);
    cudaGetSymbolAddress((void**)&hh,   g_hh);
    cudaGetSymbolAddress((void**)&hl,   g_hl);
    cudaGetSymbolAddress((void**)&wh,   g_wh);
    cudaGetSymbolAddress((void**)&wl,   g_wl);

    cudaFuncSetAttribute(gemm_mma, cudaFuncAttributeMaxDynamicSharedMemorySize, GEMM_SMEM);

    dim3 blk(256);
    const int MB = TOK / 128;   // 975

    // weight + input splits
    conv_split<<<(TOK * DD + 255) / 256, blk>>>(x, xh, xl, TOK * DD);
    conv_split<<<(49152 + 255) / 256, blk>>>(t_w_in,  wh + WO_TWIN,  wl + WO_TWIN,  49152);
    conv_split<<<(16384 + 255) / 256, blk>>>(t_w_out, wh + WO_TWOUT, wl + WO_TWOUT, 16384);
    conv_split<<<(49152 + 255) / 256, blk>>>(s_w_in,  wh + WO_SWIN,  wl + WO_SWIN,  49152);
    conv_split<<<(16384 + 255) / 256, blk>>>(s_w_out, wh + WO_SWOUT, wl + WO_SWOUT, 16384);
    conv_split<<<(65536 + 255) / 256, blk>>>(ff_w1,   wh + WO_FFW1,  wl + WO_FFW1,  65536);
    conv_split<<<(65536 + 255) / 256, blk>>>(ff_w2,   wh + WO_FFW2,  wl + WO_FFW2,  65536);

    // --- temporal attention ---
    gemm_mma<<<dim3(MB, 6), blk, GEMM_SMEM>>>(xh, xl, wh + WO_TWIN, wl + WO_TWIN, t_b_in,
                                              qkv, nullptr, nullptr, TOK, 384, 128, 0);
    temporal_attn<<<BB * NN, blk>>>(qkv, atth, attl);
    gemm_mma<<<dim3(MB, 2), blk, GEMM_SMEM>>>(atth, attl, wh + WO_TWOUT, wl + WO_TWOUT, t_b_out,
                                              proj, nullptr, nullptr, TOK, 128, 128, 0);
    add_ln<<<TOK / 8, blk>>>(x, proj, norm_t_g, norm_t_b, x1, xh, xl);

    // --- spatial attention (graph bias) ---
    gemm_mma<<<dim3(MB, 6), blk, GEMM_SMEM>>>(xh, xl, wh + WO_SWIN, wl + WO_SWIN, s_b_in,
                                              qkv, nullptr, nullptr, TOK, 384, 128, 0);
    spatial_attn<<<BB * TT * HH, blk>>>(qkv, gbias, atth, attl);
    gemm_mma<<<dim3(MB, 2), blk, GEMM_SMEM>>>(atth, attl, wh + WO_SWOUT, wl + WO_SWOUT, s_b_out,
                                              proj, nullptr, nullptr, TOK, 128, 128, 0);
    add_ln<<<TOK / 8, blk>>>(x1, proj, norm_s_g, norm_s_b, x2, xh, xl);

    // --- FFN ---
    gemm_mma<<<dim3(MB, 8), blk, GEMM_SMEM>>>(xh, xl, wh + WO_FFW1, wl + WO_FFW1, ff_b1,
                                              nullptr, hh, hl, TOK, 512, 128, 1);
    gemm_mma<<<dim3(MB, 2), blk, GEMM_SMEM>>>(hh, hl, wh + WO_FFW2, wl + WO_FFW2, ff_b2,
                                              proj, nullptr, nullptr, TOK, 128, 512, 0);
    add_ln<<<TOK / 8, blk>>>(x2, proj, norm_f_g, norm_f_b, out, nullptr, nullptr);
}